// round 2
// baseline (speedup 1.0000x reference)
#include <cuda_runtime.h>

#define B_    2
#define S_    2048
#define D_    1024
#define H_    16
#define KV_   4
#define QKB_  16
#define VB_   32
#define NROWS (B_*S_)        // 4096

// Scratch (device globals: allocation-free)
__device__ float g_q[NROWS * H_  * QKB_];   // [row][256]  col = h*16+d
__device__ float g_k[NROWS * KV_ * QKB_];   // [row][64]   col = kv*16+d
__device__ float g_v[NROWS * KV_ * VB_];    // [row][128]  col = kv*32+d
__device__ float g_sumk[NROWS * KV_];       // [row][4]
__device__ float g_vh[NROWS * H_ * VB_];    // [row][512]  col = h*32+d

__device__ __forceinline__ float sigmoidf_(float x) {
    return 1.0f / (1.0f + __expf(-x));
}

// ---------------------------------------------------------------------------
// Kernel 1: fused QKV projection + sigmoid.
// Virtual N = 448 cols: [0,256)=Wq, [256,320)=Wk, [320,448)=Wv.
// 64x64 tile, BK=16, 256 threads, 4x4 microtile (rows strided by 16).
// ---------------------------------------------------------------------------
__global__ __launch_bounds__(256) void qkv_kernel(
    const float* __restrict__ x,  const float* __restrict__ Wq,
    const float* __restrict__ Wk, const float* __restrict__ Wv)
{
    __shared__ float As[64][17];
    __shared__ float Bs[16][64];

    const int n0 = blockIdx.x * 64;
    const int m0 = blockIdx.y * 64;

    const float* W; int ldw, c0; float* Out; int ldo, oc0;
    if (n0 < 256)      { W = Wq; ldw = 256; c0 = n0;       Out = g_q; ldo = 256; oc0 = n0; }
    else if (n0 < 320) { W = Wk; ldw = 64;  c0 = 0;        Out = g_k; ldo = 64;  oc0 = 0; }
    else               { W = Wv; ldw = 128; c0 = n0 - 320; Out = g_v; ldo = 128; oc0 = n0 - 320; }

    const int tid = threadIdx.x;
    const int tx = tid & 15, ty = tid >> 4;

    float acc[4][4] = {};

    for (int k0 = 0; k0 < D_; k0 += 16) {
        { // A: 64x16 (float4 along k)
            int r = tid >> 2, c4 = (tid & 3) * 4;
            float4 va = *(const float4*)&x[(m0 + r) * D_ + k0 + c4];
            As[r][c4 + 0] = va.x; As[r][c4 + 1] = va.y;
            As[r][c4 + 2] = va.z; As[r][c4 + 3] = va.w;
        }
        { // B: 16x64
            int r = tid >> 4, c4 = (tid & 15) * 4;
            *(float4*)&Bs[r][c4] = *(const float4*)&W[(k0 + r) * ldw + c0 + c4];
        }
        __syncthreads();
        #pragma unroll
        for (int k = 0; k < 16; k++) {
            float a[4];
            #pragma unroll
            for (int i = 0; i < 4; i++) a[i] = As[ty + i * 16][k];
            float4 vb = *(const float4*)&Bs[k][tx * 4];
            float b[4] = {vb.x, vb.y, vb.z, vb.w};
            #pragma unroll
            for (int i = 0; i < 4; i++)
                #pragma unroll
                for (int j = 0; j < 4; j++)
                    acc[i][j] = fmaf(a[i], b[j], acc[i][j]);
        }
        __syncthreads();
    }

    #pragma unroll
    for (int i = 0; i < 4; i++) {
        int row = m0 + ty + i * 16;
        float4 o;
        o.x = sigmoidf_(acc[i][0]); o.y = sigmoidf_(acc[i][1]);
        o.z = sigmoidf_(acc[i][2]); o.w = sigmoidf_(acc[i][3]);
        *(float4*)&Out[row * ldo + oc0 + tx * 4] = o;
    }
}

// ---------------------------------------------------------------------------
// Kernel 2: per-(row,kv) sum of pk over QKB (for the softmax logit bias)
// ---------------------------------------------------------------------------
__global__ void sumk_kernel() {
    int i = blockIdx.x * blockDim.x + threadIdx.x;    // row*4 + kv
    if (i >= NROWS * KV_) return;
    int row = i >> 2, kv = i & 3;
    const float* p = &g_k[row * 64 + kv * 16];
    float s = 0.f;
    #pragma unroll
    for (int d = 0; d < 16; d++) s += p[d];
    g_sumk[i] = s;
}

// ---------------------------------------------------------------------------
// Kernel 3: streaming causal attention.
// logit(s,t) = 2*pq[s].pk[t] - sumk[t]  (row-constants cancel in softmax;
// bounded in (-16,32) so no max-tracking needed in fp32).
// Block = (q-tile of 128, head, batch); 1 query per thread; K/V tiles of 64
// staged in shared; all inner-loop shared reads are same-address broadcasts.
// ---------------------------------------------------------------------------
__global__ __launch_bounds__(128) void attn_kernel() {
    __shared__ float sk[64][16];
    __shared__ float sv[64][32];
    __shared__ float ssum[64];

    const int qt = blockIdx.x, h = blockIdx.y, b = blockIdx.z;
    const int s   = qt * 128 + threadIdx.x;
    const int row = b * S_ + s;
    const int kv  = h >> 2;                 // h // NREP

    float pq[16];
    {
        const float4* qp = (const float4*)&g_q[row * (H_ * QKB_) + h * QKB_];
        #pragma unroll
        for (int i = 0; i < 4; i++) {
            float4 v = qp[i];
            pq[4*i] = v.x; pq[4*i+1] = v.y; pq[4*i+2] = v.z; pq[4*i+3] = v.w;
        }
    }

    float acc[32] = {};
    float den = 0.f;

    const int tend = qt * 128 + 128;
    for (int t0 = 0; t0 < tend; t0 += 64) {
        __syncthreads();
        { // sk: 64x16 = 256 float4 -> 2/thread
            int e = threadIdx.x;
            #pragma unroll
            for (int it = 0; it < 2; it++, e += 128) {
                int r = e >> 2, c4 = (e & 3) * 4;
                *(float4*)&sk[r][c4] =
                    *(const float4*)&g_k[(b * S_ + t0 + r) * 64 + kv * 16 + c4];
            }
        }
        { // sv: 64x32 = 512 float4 -> 4/thread
            int e = threadIdx.x;
            #pragma unroll
            for (int it = 0; it < 4; it++, e += 128) {
                int r = e >> 3, c4 = (e & 7) * 4;
                *(float4*)&sv[r][c4] =
                    *(const float4*)&g_v[(b * S_ + t0 + r) * 128 + kv * 32 + c4];
            }
        }
        if (threadIdx.x < 64)
            ssum[threadIdx.x] = g_sumk[(b * S_ + t0 + threadIdx.x) * 4 + kv];
        __syncthreads();

        int nt = s - t0 + 1;          // causal: valid t count in this tile
        if (nt > 64) nt = 64;
        for (int tt = 0; tt < nt; tt++) {
            const float4* kp = (const float4*)sk[tt];
            float dot = 0.f;
            #pragma unroll
            for (int i = 0; i < 4; i++) {
                float4 kk = kp[i];
                dot = fmaf(pq[4*i  ], kk.x, dot);
                dot = fmaf(pq[4*i+1], kk.y, dot);
                dot = fmaf(pq[4*i+2], kk.z, dot);
                dot = fmaf(pq[4*i+3], kk.w, dot);
            }
            float w = __expf(2.0f * dot - ssum[tt]);
            den += w;
            const float4* vp = (const float4*)sv[tt];
            #pragma unroll
            for (int i = 0; i < 8; i++) {
                float4 vv = vp[i];
                acc[4*i  ] = fmaf(w, vv.x, acc[4*i  ]);
                acc[4*i+1] = fmaf(w, vv.y, acc[4*i+1]);
                acc[4*i+2] = fmaf(w, vv.z, acc[4*i+2]);
                acc[4*i+3] = fmaf(w, vv.w, acc[4*i+3]);
            }
        }
    }

    float inv = 1.0f / den;           // diagonal term guarantees den > 0
    float* op = &g_vh[row * (H_ * VB_) + h * VB_];
    #pragma unroll
    for (int i = 0; i < 8; i++) {
        float4 o = make_float4(acc[4*i] * inv, acc[4*i+1] * inv,
                               acc[4*i+2] * inv, acc[4*i+3] * inv);
        *(float4*)&op[4*i] = o;
    }
}

// ---------------------------------------------------------------------------
// Kernel 4: blend with e0/e1 on A-load, then [4096,512] @ Wo[512,1024].
// ---------------------------------------------------------------------------
__global__ __launch_bounds__(256) void out_kernel(
    const float* __restrict__ Wo, const float* __restrict__ e0,
    const float* __restrict__ e1, float* __restrict__ out)
{
    __shared__ float As[64][17];
    __shared__ float Bs[16][64];

    const int n0 = blockIdx.x * 64;
    const int m0 = blockIdx.y * 64;
    const int tid = threadIdx.x;
    const int tx = tid & 15, ty = tid >> 4;

    float acc[4][4] = {};

    for (int k0 = 0; k0 < 512; k0 += 16) {
        { // A with affine transform: a = e0[c] + (e1[c]-e0[c]) * vh
            int r = tid >> 2, c4 = (tid & 3) * 4;
            int c = k0 + c4;
            float4 g  = *(const float4*)&g_vh[(m0 + r) * 512 + c];
            float4 a0 = *(const float4*)&e0[c];
            float4 a1 = *(const float4*)&e1[c];
            As[r][c4 + 0] = fmaf(a1.x - a0.x, g.x, a0.x);
            As[r][c4 + 1] = fmaf(a1.y - a0.y, g.y, a0.y);
            As[r][c4 + 2] = fmaf(a1.z - a0.z, g.z, a0.z);
            As[r][c4 + 3] = fmaf(a1.w - a0.w, g.w, a0.w);
        }
        { // B: 16x64 slice of Wo
            int r = tid >> 4, c4 = (tid & 15) * 4;
            *(float4*)&Bs[r][c4] = *(const float4*)&Wo[(k0 + r) * 1024 + n0 + c4];
        }
        __syncthreads();
        #pragma unroll
        for (int k = 0; k < 16; k++) {
            float a[4];
            #pragma unroll
            for (int i = 0; i < 4; i++) a[i] = As[ty + i * 16][k];
            float4 vb = *(const float4*)&Bs[k][tx * 4];
            float b[4] = {vb.x, vb.y, vb.z, vb.w};
            #pragma unroll
            for (int i = 0; i < 4; i++)
                #pragma unroll
                for (int j = 0; j < 4; j++)
                    acc[i][j] = fmaf(a[i], b[j], acc[i][j]);
        }
        __syncthreads();
    }

    #pragma unroll
    for (int i = 0; i < 4; i++) {
        int row = m0 + ty + i * 16;
        *(float4*)&out[row * 1024 + n0 + tx * 4] =
            make_float4(acc[i][0], acc[i][1], acc[i][2], acc[i][3]);
    }
}

// ---------------------------------------------------------------------------
extern "C" void kernel_launch(void* const* d_in, const int* in_sizes, int n_in,
                              void* d_out, int out_size)
{
    const float* x  = (const float*)d_in[0];
    const float* Wq = (const float*)d_in[1];
    const float* Wk = (const float*)d_in[2];
    const float* Wv = (const float*)d_in[3];
    const float* Wo = (const float*)d_in[4];
    const float* e0 = (const float*)d_in[5];
    const float* e1 = (const float*)d_in[6];
    float* out = (float*)d_out;

    qkv_kernel<<<dim3(7, 64), 256>>>(x, Wq, Wk, Wv);   // N=448 (7x64), M=4096 (64x64)
    sumk_kernel<<<64, 256>>>();                         // 16384 sums
    attn_kernel<<<dim3(S_ / 128, H_, B_), 128>>>();     // (16,16,2)
    out_kernel<<<dim3(16, 64), 256>>>(Wo, e0, e1, out); // N=1024, M=4096
}

// round 7
// speedup vs baseline: 1.0957x; 1.0957x over previous
#include <cuda_runtime.h>

#define B_    2
#define S_    2048
#define D_    1024
#define H_    16
#define KV_   4
#define QKB_  16
#define VB_   32
#define NROWS (B_*S_)        // 4096

// Scratch (device globals: allocation-free)
__device__ float g_q[NROWS * H_  * QKB_];   // [row][256]  col = h*16+d  (pre-scaled by 2)
__device__ float g_k[NROWS * KV_ * QKB_];   // [row][64]   col = kv*16+d
__device__ float g_v[NROWS * KV_ * VB_];    // [row][128]  col = kv*32+d
__device__ float g_sumk[NROWS * KV_];       // [row][4]
__device__ float g_vh[NROWS * H_ * VB_];    // [row][512]  col = h*32+d

__device__ __forceinline__ float sigmoidf_(float x) {
    return 1.0f / (1.0f + __expf(-x));
}

// ---------------------------------------------------------------------------
// Kernel 1: fused QKV projection + sigmoid.
// Virtual N = 448 cols: [0,256)=Wq, [256,320)=Wk, [320,448)=Wv.
// Tile 128(M) x 64(N), BK=16, 256 threads, 8x4 microtile, A k-major in smem.
// ---------------------------------------------------------------------------
__global__ __launch_bounds__(256) void qkv_kernel(
    const float* __restrict__ x,  const float* __restrict__ Wq,
    const float* __restrict__ Wk, const float* __restrict__ Wv)
{
    __shared__ float As[16][132];   // [k][row], padded
    __shared__ float Bs[16][64];    // [k][col]

    const int n0 = blockIdx.x * 64;
    const int m0 = blockIdx.y * 128;

    const float* W; int ldw, c0; float* Out; int ldo, oc0;
    if (n0 < 256)      { W = Wq; ldw = 256; c0 = n0;       Out = g_q; ldo = 256; oc0 = n0; }
    else if (n0 < 320) { W = Wk; ldw = 64;  c0 = 0;        Out = g_k; ldo = 64;  oc0 = 0; }
    else               { W = Wv; ldw = 128; c0 = n0 - 320; Out = g_v; ldo = 128; oc0 = n0 - 320; }

    const int tid = threadIdx.x;
    const int tx = tid & 15;        // col group: cols tx*4 .. tx*4+3
    const int ty = tid >> 4;        // row group: rows ty*8 .. ty*8+7

    float acc[8][4] = {};

    for (int k0 = 0; k0 < D_; k0 += 16) {
        // A: 128 rows x 16 k -> 512 float4, 2 per thread; store transposed
        #pragma unroll
        for (int it = 0; it < 2; it++) {
            int e = tid * 2 + it;
            int r = e >> 2, c4 = (e & 3) * 4;
            float4 va = *(const float4*)&x[(m0 + r) * D_ + k0 + c4];
            As[c4 + 0][r] = va.x; As[c4 + 1][r] = va.y;
            As[c4 + 2][r] = va.z; As[c4 + 3][r] = va.w;
        }
        // B: 16 k x 64 cols -> 256 float4, 1 per thread
        {
            int r = tid >> 4, c4 = (tid & 15) * 4;
            *(float4*)&Bs[r][c4] = *(const float4*)&W[(k0 + r) * ldw + c0 + c4];
        }
        __syncthreads();
        #pragma unroll
        for (int k = 0; k < 16; k++) {
            float4 a0 = *(const float4*)&As[k][ty * 8];
            float4 a1 = *(const float4*)&As[k][ty * 8 + 4];
            float a[8] = {a0.x, a0.y, a0.z, a0.w, a1.x, a1.y, a1.z, a1.w};
            float4 vb = *(const float4*)&Bs[k][tx * 4];
            float b[4] = {vb.x, vb.y, vb.z, vb.w};
            #pragma unroll
            for (int i = 0; i < 8; i++)
                #pragma unroll
                for (int j = 0; j < 4; j++)
                    acc[i][j] = fmaf(a[i], b[j], acc[i][j]);
        }
        __syncthreads();
    }

    const float qscale = (n0 < 256) ? 2.0f : 1.0f;   // fold 2*pq.pk into pq
    #pragma unroll
    for (int i = 0; i < 8; i++) {
        int row = m0 + ty * 8 + i;
        float4 o;
        o.x = qscale * sigmoidf_(acc[i][0]); o.y = qscale * sigmoidf_(acc[i][1]);
        o.z = qscale * sigmoidf_(acc[i][2]); o.w = qscale * sigmoidf_(acc[i][3]);
        *(float4*)&Out[row * ldo + oc0 + tx * 4] = o;
    }
}

// ---------------------------------------------------------------------------
// Kernel 2: per-(row,kv) sum of pk over QKB
// ---------------------------------------------------------------------------
__global__ void sumk_kernel() {
    int i = blockIdx.x * blockDim.x + threadIdx.x;    // row*4 + kv
    if (i >= NROWS * KV_) return;
    int row = i >> 2, kv = i & 3;
    const float* p = &g_k[row * 64 + kv * 16];
    float s = 0.f;
    #pragma unroll
    for (int d = 0; d < 16; d++) s += p[d];
    g_sumk[i] = s;
}

// ---------------------------------------------------------------------------
// Kernel 3: streaming causal attention.
// logit(s,t) = (2*pq[s]).pk[t] - sumk[t]  (pq pre-scaled by 2 in kernel 1;
// row-constant terms cancel in softmax; logits bounded -> no max-tracking).
// 1 query/thread, 128 q/block; K/V tiles of 64 in shared.
// Full tiles (no causal check) unrolled x2 for ILP; last 2 tiles per-thread.
// ---------------------------------------------------------------------------
__global__ __launch_bounds__(128) void attn_kernel() {
    __shared__ float sk[64][16];
    __shared__ float sv[64][32];
    __shared__ float ssum[64];

    const int qt = blockIdx.x, h = blockIdx.y, b = blockIdx.z;
    const int s   = qt * 128 + threadIdx.x;
    const int row = b * S_ + s;
    const int kv  = h >> 2;

    float pq[16];
    {
        const float4* qp = (const float4*)&g_q[row * (H_ * QKB_) + h * QKB_];
        #pragma unroll
        for (int i = 0; i < 4; i++) {
            float4 v = qp[i];
            pq[4*i] = v.x; pq[4*i+1] = v.y; pq[4*i+2] = v.z; pq[4*i+3] = v.w;
        }
    }

    float acc[32] = {};
    float den = 0.f;

    const int tfull = qt * 128;        // tiles strictly below the diagonal block
    int t0 = 0;
    for (; t0 < tfull + 128; t0 += 64) {
        __syncthreads();
        { // sk: 64x16 = 256 float4 -> 2/thread
            int e = threadIdx.x;
            #pragma unroll
            for (int it = 0; it < 2; it++, e += 128) {
                int r = e >> 2, c4 = (e & 3) * 4;
                *(float4*)&sk[r][c4] =
                    *(const float4*)&g_k[(b * S_ + t0 + r) * 64 + kv * 16 + c4];
            }
        }
        { // sv: 64x32 = 512 float4 -> 4/thread
            int e = threadIdx.x;
            #pragma unroll
            for (int it = 0; it < 4; it++, e += 128) {
                int r = e >> 3, c4 = (e & 7) * 4;
                *(float4*)&sv[r][c4] =
                    *(const float4*)&g_v[(b * S_ + t0 + r) * 128 + kv * 32 + c4];
            }
        }
        if (threadIdx.x < 64)
            ssum[threadIdx.x] = g_sumk[(b * S_ + t0 + threadIdx.x) * 4 + kv];
        __syncthreads();

        if (t0 < tfull) {
            // FULL tile: all 64 keys valid for every thread; 2 keys/iter for ILP
            #pragma unroll 2
            for (int tt = 0; tt < 64; tt += 2) {
                const float4* kp0 = (const float4*)sk[tt];
                const float4* kp1 = (const float4*)sk[tt + 1];
                float dot0 = 0.f, dot1 = 0.f;
                #pragma unroll
                for (int i = 0; i < 4; i++) {
                    float4 k0 = kp0[i], k1 = kp1[i];
                    dot0 = fmaf(pq[4*i  ], k0.x, dot0);
                    dot1 = fmaf(pq[4*i  ], k1.x, dot1);
                    dot0 = fmaf(pq[4*i+1], k0.y, dot0);
                    dot1 = fmaf(pq[4*i+1], k1.y, dot1);
                    dot0 = fmaf(pq[4*i+2], k0.z, dot0);
                    dot1 = fmaf(pq[4*i+2], k1.z, dot1);
                    dot0 = fmaf(pq[4*i+3], k0.w, dot0);
                    dot1 = fmaf(pq[4*i+3], k1.w, dot1);
                }
                float w0 = __expf(dot0 - ssum[tt]);
                float w1 = __expf(dot1 - ssum[tt + 1]);
                den += w0 + w1;
                const float4* vp0 = (const float4*)sv[tt];
                const float4* vp1 = (const float4*)sv[tt + 1];
                #pragma unroll
                for (int i = 0; i < 8; i++) {
                    float4 v0 = vp0[i], v1 = vp1[i];
                    acc[4*i  ] = fmaf(w1, v1.x, fmaf(w0, v0.x, acc[4*i  ]));
                    acc[4*i+1] = fmaf(w1, v1.y, fmaf(w0, v0.y, acc[4*i+1]));
                    acc[4*i+2] = fmaf(w1, v1.z, fmaf(w0, v0.z, acc[4*i+2]));
                    acc[4*i+3] = fmaf(w1, v1.w, fmaf(w0, v0.w, acc[4*i+3]));
                }
            }
        } else {
            // PARTIAL (diagonal-block) tile: per-thread causal bound
            int nt = s - t0 + 1;
            if (nt > 64) nt = 64;
            for (int tt = 0; tt < nt; tt++) {
                const float4* kp = (const float4*)sk[tt];
                float dot = 0.f;
                #pragma unroll
                for (int i = 0; i < 4; i++) {
                    float4 kk = kp[i];
                    dot = fmaf(pq[4*i  ], kk.x, dot);
                    dot = fmaf(pq[4*i+1], kk.y, dot);
                    dot = fmaf(pq[4*i+2], kk.z, dot);
                    dot = fmaf(pq[4*i+3], kk.w, dot);
                }
                float w = __expf(dot - ssum[tt]);
                den += w;
                const float4* vp = (const float4*)sv[tt];
                #pragma unroll
                for (int i = 0; i < 8; i++) {
                    float4 vv = vp[i];
                    acc[4*i  ] = fmaf(w, vv.x, acc[4*i  ]);
                    acc[4*i+1] = fmaf(w, vv.y, acc[4*i+1]);
                    acc[4*i+2] = fmaf(w, vv.z, acc[4*i+2]);
                    acc[4*i+3] = fmaf(w, vv.w, acc[4*i+3]);
                }
            }
        }
    }

    float inv = 1.0f / den;           // diagonal term guarantees den > 0
    float* op = &g_vh[row * (H_ * VB_) + h * VB_];
    #pragma unroll
    for (int i = 0; i < 8; i++) {
        *(float4*)&op[4*i] = make_float4(acc[4*i] * inv, acc[4*i+1] * inv,
                                         acc[4*i+2] * inv, acc[4*i+3] * inv);
    }
}

// ---------------------------------------------------------------------------
// Kernel 4: blend with e0/e1 on A-load, then [4096,512] @ Wo[512,1024].
// Tile 128x128, BK=16, 256 threads, 8x8 microtile, A k-major in smem.
// ---------------------------------------------------------------------------
__global__ __launch_bounds__(256) void out_kernel(
    const float* __restrict__ Wo, const float* __restrict__ e0,
    const float* __restrict__ e1, float* __restrict__ out)
{
    __shared__ float As[16][132];    // [k][row], padded
    __shared__ float Bs[16][128];    // [k][col]

    const int n0 = blockIdx.x * 128;
    const int m0 = blockIdx.y * 128;
    const int tid = threadIdx.x;
    const int tx = tid & 15;         // col group: cols tx*8..tx*8+7
    const int ty = tid >> 4;         // row group: rows ty*8..ty*8+7

    float acc[8][8] = {};

    for (int k0 = 0; k0 < 512; k0 += 16) {
        // A with affine blend, transposed store: 128x16 -> 2 float4/thread
        #pragma unroll
        for (int it = 0; it < 2; it++) {
            int e = tid * 2 + it;
            int r = e >> 2, c4 = (e & 3) * 4;
            int c = k0 + c4;
            float4 g  = *(const float4*)&g_vh[(m0 + r) * 512 + c];
            float4 a0 = *(const float4*)&e0[c];
            float4 a1 = *(const float4*)&e1[c];
            As[c4 + 0][r] = fmaf(a1.x - a0.x, g.x, a0.x);
            As[c4 + 1][r] = fmaf(a1.y - a0.y, g.y, a0.y);
            As[c4 + 2][r] = fmaf(a1.z - a0.z, g.z, a0.z);
            As[c4 + 3][r] = fmaf(a1.w - a0.w, g.w, a0.w);
        }
        // B: 16x128 -> 2 float4/thread
        #pragma unroll
        for (int it = 0; it < 2; it++) {
            int e = tid * 2 + it;
            int r = e >> 5, c4 = (e & 31) * 4;
            *(float4*)&Bs[r][c4] = *(const float4*)&Wo[(k0 + r) * 1024 + n0 + c4];
        }
        __syncthreads();
        #pragma unroll
        for (int k = 0; k < 16; k++) {
            float4 a0 = *(const float4*)&As[k][ty * 8];
            float4 a1 = *(const float4*)&As[k][ty * 8 + 4];
            float a[8] = {a0.x, a0.y, a0.z, a0.w, a1.x, a1.y, a1.z, a1.w};
            float4 b0 = *(const float4*)&Bs[k][tx * 8];
            float4 b1 = *(const float4*)&Bs[k][tx * 8 + 4];
            float b[8] = {b0.x, b0.y, b0.z, b0.w, b1.x, b1.y, b1.z, b1.w};
            #pragma unroll
            for (int i = 0; i < 8; i++)
                #pragma unroll
                for (int j = 0; j < 8; j++)
                    acc[i][j] = fmaf(a[i], b[j], acc[i][j]);
        }
        __syncthreads();
    }

    #pragma unroll
    for (int i = 0; i < 8; i++) {
        int row = m0 + ty * 8 + i;
        *(float4*)&out[row * 1024 + n0 + tx * 8] =
            make_float4(acc[i][0], acc[i][1], acc[i][2], acc[i][3]);
        *(float4*)&out[row * 1024 + n0 + tx * 8 + 4] =
            make_float4(acc[i][4], acc[i][5], acc[i][6], acc[i][7]);
    }
}

// ---------------------------------------------------------------------------
extern "C" void kernel_launch(void* const* d_in, const int* in_sizes, int n_in,
                              void* d_out, int out_size)
{
    const float* x  = (const float*)d_in[0];
    const float* Wq = (const float*)d_in[1];
    const float* Wk = (const float*)d_in[2];
    const float* Wv = (const float*)d_in[3];
    const float* Wo = (const float*)d_in[4];
    const float* e0 = (const float*)d_in[5];
    const float* e1 = (const float*)d_in[6];
    float* out = (float*)d_out;

    qkv_kernel<<<dim3(7, 32), 256>>>(x, Wq, Wk, Wv);   // N=448 (7x64), M=4096 (32x128)
    sumk_kernel<<<64, 256>>>();                         // 16384 sums
    attn_kernel<<<dim3(S_ / 128, H_, B_), 128>>>();     // (16,16,2)
    out_kernel<<<dim3(8, 32), 256>>>(Wo, e0, e1, out);  // N=1024 (8x128), M=4096
}